// round 1
// baseline (speedup 1.0000x reference)
#include <cuda_runtime.h>
#include <math.h>

#define NMAX 100000
#define C 128
#define C2 256
#define PP 64
#define DIST_TH 0.1f

// ---------------- scratch (device globals: allocation-free rule) --------------
__device__ float g_h [(size_t)NMAX * C2];   // 102.4 MB
__device__ float g_h2[(size_t)NMAX * C];    // 51.2 MB
__device__ float g_a [(size_t)NMAX * C];    // 51.2 MB
__device__ unsigned int g_maxU[C];
__device__ float g_num_on [PP * C];
__device__ float g_den_on [PP * C];
__device__ float g_num_off[PP * C];
__device__ float g_den_off[PP * C];

// monotone float<->uint key for atomicMax over signed floats
__device__ __forceinline__ unsigned int fkey(float f) {
    unsigned int u = __float_as_uint(f);
    return (u & 0x80000000u) ? ~u : (u | 0x80000000u);
}
__device__ __forceinline__ float funkey(unsigned int k) {
    unsigned int u = (k & 0x80000000u) ? (k & 0x7fffffffu) : ~k;
    return __uint_as_float(u);
}

// ---------------- init ----------------
__global__ void init_kernel() {
    int t = blockIdx.x * blockDim.x + threadIdx.x;
    int stride = gridDim.x * blockDim.x;
    if (t < C) g_maxU[t] = 0u;  // 0 is below every valid key
    for (int i = t; i < PP * C; i += stride) {
        g_num_on[i] = 0.f; g_den_on[i] = 0.f;
        g_num_off[i] = 0.f; g_den_off[i] = 0.f;
    }
}

// ---------------- 128x128-tile SGEMM, 256 thr, 8x8/thread -------------------
// C = A[MxK] * B[KxN]; epilogue: RELU_SB -> relu(acc*scale[col]+bias[col])
// DO_MAX -> also per-column global max of stored values (att kernel)
template<int RELU_SB, int DO_MAX>
__global__ __launch_bounds__(256)
void sgemm_kernel(const float* __restrict__ A, const float* __restrict__ B,
                  const float* __restrict__ scale, const float* __restrict__ bias,
                  float* __restrict__ Cm, int M, int K, int Nn)
{
    __shared__ float As[16][128];
    __shared__ float Bs[16][128];
    __shared__ unsigned int smax[128];

    int tid = threadIdx.x;
    int tx = tid & 15, ty = tid >> 4;
    int m0 = blockIdx.x * 128;
    int n0 = blockIdx.y * 128;

    float acc[8][8];
#pragma unroll
    for (int i = 0; i < 8; i++)
#pragma unroll
        for (int j = 0; j < 8; j++) acc[i][j] = 0.f;

    if (DO_MAX && tid < 128) smax[tid] = 0u;

    for (int k0 = 0; k0 < K; k0 += 16) {
        __syncthreads();
        // A tile -> As[k][m] (transposed), zero-pad rows >= M
#pragma unroll
        for (int i = 0; i < 2; i++) {
            int l = tid + i * 256;        // 0..511
            int row = l >> 2;             // 0..127
            int kg = (l & 3) * 4;
            int gm = m0 + row;
            float4 v = make_float4(0.f, 0.f, 0.f, 0.f);
            if (gm < M) v = *(const float4*)(A + (size_t)gm * K + k0 + kg);
            As[kg + 0][row] = v.x; As[kg + 1][row] = v.y;
            As[kg + 2][row] = v.z; As[kg + 3][row] = v.w;
        }
        // B tile -> Bs[k][n]
#pragma unroll
        for (int i = 0; i < 2; i++) {
            int l = tid + i * 256;
            int kr = l >> 5;              // 0..15
            int ng = (l & 31) * 4;
            *(float4*)&Bs[kr][ng] =
                *(const float4*)(B + (size_t)(k0 + kr) * Nn + n0 + ng);
        }
        __syncthreads();
#pragma unroll
        for (int kk = 0; kk < 16; kk++) {
            float a[8], b[8];
            *(float4*)&a[0] = *(const float4*)&As[kk][ty * 8];
            *(float4*)&a[4] = *(const float4*)&As[kk][ty * 8 + 4];
            *(float4*)&b[0] = *(const float4*)&Bs[kk][tx * 8];
            *(float4*)&b[4] = *(const float4*)&Bs[kk][tx * 8 + 4];
#pragma unroll
            for (int i = 0; i < 8; i++)
#pragma unroll
                for (int j = 0; j < 8; j++)
                    acc[i][j] = fmaf(a[i], b[j], acc[i][j]);
        }
    }

    // epilogue
    float sc[8], bi[8];
    if (RELU_SB) {
#pragma unroll
        for (int j = 0; j < 8; j++) {
            int col = n0 + tx * 8 + j;
            sc[j] = scale[col];
            bi[j] = bias[col];
        }
    }
    float vals[8][8];
#pragma unroll
    for (int i = 0; i < 8; i++) {
#pragma unroll
        for (int j = 0; j < 8; j++) {
            float v = acc[i][j];
            if (RELU_SB) v = fmaxf(fmaf(v, sc[j], bi[j]), 0.f);
            vals[i][j] = v;
        }
        int gm = m0 + ty * 8 + i;
        if (gm < M) {
            float* dst = Cm + (size_t)gm * Nn + n0 + tx * 8;
            *(float4*)dst       = *(float4*)&vals[i][0];
            *(float4*)(dst + 4) = *(float4*)&vals[i][4];
        }
    }

    if (DO_MAX) {
#pragma unroll
        for (int j = 0; j < 8; j++) {
            float mx = -INFINITY;
            bool any = false;
#pragma unroll
            for (int i = 0; i < 8; i++) {
                if (m0 + ty * 8 + i < M) { mx = fmaxf(mx, vals[i][j]); any = true; }
            }
            if (any) atomicMax(&smax[tx * 8 + j], fkey(mx));
        }
        __syncthreads();
        if (tid < 128) atomicMax(&g_maxU[n0 + tid], smax[tid]);
    }
}

// ---------------- logit = h2 @ W3 + b3 -> out[0..M) -------------------------
__global__ void logit_kernel(const float* __restrict__ h2,
                             const float* __restrict__ W3,
                             const float* __restrict__ b3,
                             float* __restrict__ out, int M)
{
    __shared__ float w[C];
    if (threadIdx.x < C) w[threadIdx.x] = W3[threadIdx.x];
    __syncthreads();
    int lane = threadIdx.x & 31;
    int wid = (blockIdx.x * blockDim.x + threadIdx.x) >> 5;
    int nw = (gridDim.x * blockDim.x) >> 5;
    float bb = b3[0];
    for (int n = wid; n < M; n += nw) {
        const float* r = h2 + (size_t)n * C;
        float s = 0.f;
#pragma unroll
        for (int q = 0; q < 4; q++)
            s = fmaf(r[lane + q * 32], w[lane + q * 32], s);
#pragma unroll
        for (int o = 16; o; o >>= 1) s += __shfl_xor_sync(0xffffffffu, s, o);
        if (lane == 0) out[n] = s + bb;
    }
}

// ---------------- sparse masked pooling scatter ------------------------------
__global__ void pool_kernel(const float* __restrict__ xyz,
                            const float* __restrict__ pc,
                            const float* __restrict__ pn,
                            const float* __restrict__ pmn,
                            const float* __restrict__ pmx,
                            const float* __restrict__ logit, int M)
{
    __shared__ float s_n0[PP], s_n1[PP], s_n2[PP], s_off[PP];
    __shared__ float s_mn0[PP], s_mn1[PP], s_mx0[PP], s_mx1[PP];
    __shared__ float s_amax[C];
    int t = threadIdx.x;
    if (t < PP) {
        float a0 = pn[t * 3], a1 = pn[t * 3 + 1], a2 = pn[t * 3 + 2];
        s_n0[t] = a0; s_n1[t] = a1; s_n2[t] = a2;
        s_off[t] = pc[t * 3] * a0 + pc[t * 3 + 1] * a1 + pc[t * 3 + 2] * a2;
        s_mn0[t] = pmn[t * 3]; s_mn1[t] = pmn[t * 3 + 1];
        s_mx0[t] = pmx[t * 3]; s_mx1[t] = pmx[t * 3 + 1];
    }
    if (t < C) s_amax[t] = funkey(g_maxU[t]);
    __syncthreads();

    int n = blockIdx.x * blockDim.x + t;
    int stride = gridDim.x * blockDim.x;
    for (; n < M; n += stride) {
        float x = xyz[n * 3], y = xyz[n * 3 + 1], z = xyz[n * 3 + 2];
        unsigned long long mask = 0ull;
#pragma unroll
        for (int p = 0; p < PP; p++) {
            float proj = x * s_n0[p] + y * s_n1[p] + z * s_n2[p];
            bool hit = (fabsf(proj - s_off[p]) < DIST_TH) &&
                       (x >= s_mn0[p]) && (x < s_mx0[p]) &&
                       (y >= s_mn1[p]) && (y < s_mx1[p]);
            if (hit) mask |= (1ull << p);
        }
        if (!mask) continue;
        bool on = logit[n] > 0.0f;
        float* numB = on ? g_num_on : g_num_off;
        float* denB = on ? g_den_on : g_den_off;
        const float* ar = g_a + (size_t)n * C;
        const float* hr = g_h2 + (size_t)n * C;
        for (int c = 0; c < C; c += 4) {
            float4 a4 = *(const float4*)(ar + c);
            float4 h4 = *(const float4*)(hr + c);
            float e0 = expf(a4.x - s_amax[c + 0]);
            float e1 = expf(a4.y - s_amax[c + 1]);
            float e2 = expf(a4.z - s_amax[c + 2]);
            float e3 = expf(a4.w - s_amax[c + 3]);
            unsigned long long mm = mask;
            while (mm) {
                int p = __ffsll(mm) - 1;
                mm &= mm - 1;
                float* dn = denB + p * C + c;
                float* nm = numB + p * C + c;
                atomicAdd(dn + 0, e0); atomicAdd(dn + 1, e1);
                atomicAdd(dn + 2, e2); atomicAdd(dn + 3, e3);
                atomicAdd(nm + 0, e0 * h4.x); atomicAdd(nm + 1, e1 * h4.y);
                atomicAdd(nm + 2, e2 * h4.z); atomicAdd(nm + 3, e3 * h4.w);
            }
        }
    }
}

// ---------------- finalize: agg -> relu(agg@Wm+bm), concat ori --------------
__global__ void finalize_kernel(const float* __restrict__ Wm,
                                const float* __restrict__ bm,
                                const float* __restrict__ pc,
                                const float* __restrict__ pn,
                                const float* __restrict__ pmn,
                                const float* __restrict__ pmx,
                                float* __restrict__ out, int M)
{
    int p = blockIdx.x;     // 64
    int c = threadIdx.x;    // 128
    __shared__ float aggOn[C], aggOff[C];
    aggOn[c]  = g_num_on [p * C + c] / (g_den_on [p * C + c] + 1e-9f);
    aggOff[c] = g_num_off[p * C + c] / (g_den_off[p * C + c] + 1e-9f);
    __syncthreads();
    float so = 0.f, sf = 0.f;
#pragma unroll 8
    for (int k = 0; k < C; k++) {
        float w = Wm[k * C + c];
        so = fmaf(aggOn[k], w, so);
        sf = fmaf(aggOff[k], w, sf);
    }
    float bb = bm[c];
    float* onRow  = out + M + (size_t)p * (C + 12);
    float* offRow = out + M + (size_t)PP * (C + 12) + (size_t)p * (C + 12);
    onRow[c]  = fmaxf(so + bb, 0.f);
    offRow[c] = fmaxf(sf + bb, 0.f);
    if (c < 12) {
        int axis = c % 3, grp = c / 3;
        const float* src = (grp == 0) ? pc : (grp == 1) ? pn : (grp == 2) ? pmn : pmx;
        float v = src[p * 3 + axis];
        onRow[C + c] = v;
        offRow[C + c] = v;
    }
}

// ---------------- launch ----------------
extern "C" void kernel_launch(void* const* d_in, const int* in_sizes, int n_in,
                              void* d_out, int out_size)
{
    const float* feature = (const float*)d_in[0];
    const float* xyz     = (const float*)d_in[1];
    const float* pc      = (const float*)d_in[2];
    const float* pn      = (const float*)d_in[3];
    const float* pmn     = (const float*)d_in[4];
    const float* pmx     = (const float*)d_in[5];
    const float* W1      = (const float*)d_in[6];
    const float* s1      = (const float*)d_in[7];
    const float* b1      = (const float*)d_in[8];
    const float* W2      = (const float*)d_in[9];
    const float* s2      = (const float*)d_in[10];
    const float* b2      = (const float*)d_in[11];
    const float* W3      = (const float*)d_in[12];
    const float* b3      = (const float*)d_in[13];
    const float* Wa      = (const float*)d_in[14];
    const float* Wm      = (const float*)d_in[15];
    const float* bm      = (const float*)d_in[16];

    int M = in_sizes[1] / 3;            // N = 100000
    float* out = (float*)d_out;

    float *hP, *h2P, *aP;
    cudaGetSymbolAddress((void**)&hP,  g_h);
    cudaGetSymbolAddress((void**)&h2P, g_h2);
    cudaGetSymbolAddress((void**)&aP,  g_a);

    int gx = (M + 127) / 128;           // 782

    init_kernel<<<32, 256>>>();
    // FC1: h = relu((feature@W1)*s1+b1)   [M,128]x[128,256]
    sgemm_kernel<1, 0><<<dim3(gx, 2), 256>>>(feature, W1, s1, b1, hP, M, C, C2);
    // FC2: h2 = relu((h@W2)*s2+b2)        [M,256]x[256,128]
    sgemm_kernel<1, 0><<<dim3(gx, 1), 256>>>(hP, W2, s2, b2, h2P, M, C2, C);
    // logit -> out[0..M)
    logit_kernel<<<1024, 256>>>(h2P, W3, b3, out, M);
    // a = h2@Wa  + per-channel global max  [M,128]x[128,128]
    sgemm_kernel<0, 1><<<dim3(gx, 1), 256>>>(h2P, Wa, nullptr, nullptr, aP, M, C, C);
    // sparse masked softmax pooling scatter
    pool_kernel<<<512, 256>>>(xyz, pc, pn, pmn, pmx, out, M);
    // tiny per-plane GEMM + ori concat
    finalize_kernel<<<PP, 128>>>(Wm, bm, pc, pn, pmn, pmx, out, M);
}

// round 2
// speedup vs baseline: 1.0965x; 1.0965x over previous
#include <cuda_runtime.h>
#include <math.h>

#define NMAX 100000
#define C 128
#define C2 256
#define PP 64
#define DIST_TH 0.1f

// ---------------- scratch (device globals: allocation-free rule) --------------
__device__ float g_h [(size_t)NMAX * C2];   // 102.4 MB
__device__ float g_h2[(size_t)NMAX * C];    // 51.2 MB
__device__ float g_a [(size_t)NMAX * C];    // compacted att activations
__device__ int   g_idx[NMAX];
__device__ unsigned long long g_maskArr[NMAX];
__device__ int   g_cnt;
__device__ unsigned int g_maxU[C];
__device__ float g_num_on [PP * C];
__device__ float g_den_on [PP * C];
__device__ float g_num_off[PP * C];
__device__ float g_den_off[PP * C];

// monotone float<->uint key for atomicMax over signed floats
__device__ __forceinline__ unsigned int fkey(float f) {
    unsigned int u = __float_as_uint(f);
    return (u & 0x80000000u) ? ~u : (u | 0x80000000u);
}
__device__ __forceinline__ float funkey(unsigned int k) {
    unsigned int u = (k & 0x80000000u) ? (k & 0x7fffffffu) : ~k;
    return __uint_as_float(u);
}

// packed fp32x2 helpers (ptxas never auto-generates FFMA2)
#define DUPF(d, s) asm("mov.b64 %0, {%1, %1};" : "=l"(d) : "r"(__float_as_uint(s)))
#define FMA2(d, a, b) asm("fma.rn.f32x2 %0, %1, %2, %0;" : "+l"(d) : "l"(a), "l"(b))
#define UNPK(lo, hi, v) asm("mov.b64 {%0, %1}, %2;" : "=r"(lo), "=r"(hi) : "l"(v))

// ---------------- init ----------------
__global__ void init_kernel() {
    int t = blockIdx.x * blockDim.x + threadIdx.x;
    int stride = gridDim.x * blockDim.x;
    if (t == 0) g_cnt = 0;
    if (t < C) g_maxU[t] = 0u;
    for (int i = t; i < PP * C; i += stride) {
        g_num_on[i] = 0.f; g_den_on[i] = 0.f;
        g_num_off[i] = 0.f; g_den_off[i] = 0.f;
    }
}

// ---------------- 128x128-tile SGEMM with f32x2 FMA, 256 thr, 8x8/thread ----
// RELU_SB: relu(acc*scale[col]+bias[col]); DO_MAX: global per-col max of stored
// values; INDIRECT: A rows gathered via g_idx, M limited by g_cnt;
// WRITE_LOGIT: also emit h2@W3+b3 per row (requires Nn==128, n0==0).
template<int RELU_SB, int DO_MAX, int INDIRECT, int WRITE_LOGIT>
__global__ __launch_bounds__(256)
void sgemm2_kernel(const float* __restrict__ A, const float* __restrict__ B,
                   const float* __restrict__ scale, const float* __restrict__ bias,
                   const float* __restrict__ W3, const float* __restrict__ b3,
                   float* __restrict__ logitOut,
                   float* __restrict__ Cm, int M, int K, int Nn)
{
    __shared__ __align__(16) float As[16][128];
    __shared__ __align__(16) float Bs[16][128];
    __shared__ unsigned int smax[128];

    int Meff = M;
    if (INDIRECT) {
        Meff = g_cnt;
        if ((int)(blockIdx.x * 128) >= Meff) return;
    }

    int tid = threadIdx.x;
    int tx = tid & 15, ty = tid >> 4;
    int m0 = blockIdx.x * 128;
    int n0 = blockIdx.y * 128;

    if (DO_MAX && tid < 128) smax[tid] = 0u;

    // per-thread load coordinates (each thread loads 2 A-float4, 2 B-float4)
    int aRow = tid >> 2;            // 0..63 ; second at +64
    int aKg  = (tid & 3) * 4;       // 0,4,8,12
    int bKr  = tid >> 5;            // 0..7 ; second at +8
    int bNg  = (tid & 31) * 4;

    const float* aP0 = nullptr; const float* aP1 = nullptr;
    {
        int gm0 = m0 + aRow, gm1 = m0 + aRow + 64;
        if (gm0 < Meff) aP0 = A + (size_t)(INDIRECT ? g_idx[gm0] : gm0) * K;
        if (gm1 < Meff) aP1 = A + (size_t)(INDIRECT ? g_idx[gm1] : gm1) * K;
    }
    const float* bP0 = B + (size_t)bKr * Nn + n0 + bNg;
    const float* bP1 = B + (size_t)(bKr + 8) * Nn + n0 + bNg;

    unsigned long long acc2[8][4];
#pragma unroll
    for (int i = 0; i < 8; i++)
#pragma unroll
        for (int j = 0; j < 4; j++) acc2[i][j] = 0ull;

    const float4 f40 = make_float4(0.f, 0.f, 0.f, 0.f);
    float4 ra0, ra1, rb0, rb1;
    ra0 = aP0 ? *(const float4*)(aP0 + aKg) : f40;
    ra1 = aP1 ? *(const float4*)(aP1 + aKg) : f40;
    rb0 = *(const float4*)(bP0);
    rb1 = *(const float4*)(bP1);

    for (int k0 = 0; k0 < K; k0 += 16) {
        __syncthreads();
        As[aKg + 0][aRow] = ra0.x; As[aKg + 1][aRow] = ra0.y;
        As[aKg + 2][aRow] = ra0.z; As[aKg + 3][aRow] = ra0.w;
        As[aKg + 0][aRow + 64] = ra1.x; As[aKg + 1][aRow + 64] = ra1.y;
        As[aKg + 2][aRow + 64] = ra1.z; As[aKg + 3][aRow + 64] = ra1.w;
        *(float4*)&Bs[bKr][bNg]     = rb0;
        *(float4*)&Bs[bKr + 8][bNg] = rb1;
        __syncthreads();

        int kn = k0 + 16;
        if (kn < K) {
            ra0 = aP0 ? *(const float4*)(aP0 + kn + aKg) : f40;
            ra1 = aP1 ? *(const float4*)(aP1 + kn + aKg) : f40;
            rb0 = *(const float4*)(bP0 + (size_t)kn * Nn);
            rb1 = *(const float4*)(bP1 + (size_t)kn * Nn);
        }

#pragma unroll
        for (int kk = 0; kk < 16; kk++) {
            float4 af0 = *(const float4*)&As[kk][ty * 8];
            float4 af1 = *(const float4*)&As[kk][ty * 8 + 4];
            ulonglong2 bq0 = *(const ulonglong2*)&Bs[kk][tx * 8];
            ulonglong2 bq1 = *(const ulonglong2*)&Bs[kk][tx * 8 + 4];
            unsigned long long bb[4] = {bq0.x, bq0.y, bq1.x, bq1.y};
            unsigned long long ad[8];
            DUPF(ad[0], af0.x); DUPF(ad[1], af0.y);
            DUPF(ad[2], af0.z); DUPF(ad[3], af0.w);
            DUPF(ad[4], af1.x); DUPF(ad[5], af1.y);
            DUPF(ad[6], af1.z); DUPF(ad[7], af1.w);
#pragma unroll
            for (int i = 0; i < 8; i++)
#pragma unroll
                for (int j = 0; j < 4; j++)
                    FMA2(acc2[i][j], ad[i], bb[j]);
        }
    }

    // ---------------- epilogue ----------------
    float sc[8], bi[8];
    if (RELU_SB) {
#pragma unroll
        for (int j = 0; j < 8; j++) {
            int col = n0 + tx * 8 + j;
            sc[j] = scale[col];
            bi[j] = bias[col];
        }
    }
    float w3r[8];
    if (WRITE_LOGIT) {
#pragma unroll
        for (int j = 0; j < 8; j++) w3r[j] = W3[tx * 8 + j];
    }
    float colmax[8];
    bool anyv = false;
    if (DO_MAX) {
#pragma unroll
        for (int j = 0; j < 8; j++) colmax[j] = -INFINITY;
    }

#pragma unroll
    for (int i = 0; i < 8; i++) {
        int gm = m0 + ty * 8 + i;
        float v[8];
#pragma unroll
        for (int jp = 0; jp < 4; jp++) {
            unsigned int lo, hi;
            UNPK(lo, hi, acc2[i][jp]);
            v[2 * jp]     = __uint_as_float(lo);
            v[2 * jp + 1] = __uint_as_float(hi);
        }
        if (RELU_SB) {
#pragma unroll
            for (int j = 0; j < 8; j++) v[j] = fmaxf(fmaf(v[j], sc[j], bi[j]), 0.f);
        }
        bool valid = gm < Meff;
        if (valid) {
            float* dst = Cm + (size_t)gm * Nn + n0 + tx * 8;
            *(float4*)dst       = *(float4*)&v[0];
            *(float4*)(dst + 4) = *(float4*)&v[4];
        }
        if (DO_MAX && valid) {
            anyv = true;
#pragma unroll
            for (int j = 0; j < 8; j++) colmax[j] = fmaxf(colmax[j], v[j]);
        }
        if (WRITE_LOGIT) {
            float p = 0.f;
#pragma unroll
            for (int j = 0; j < 8; j++) p = fmaf(v[j], w3r[j], p);
            p += __shfl_xor_sync(0xffffffffu, p, 1);
            p += __shfl_xor_sync(0xffffffffu, p, 2);
            p += __shfl_xor_sync(0xffffffffu, p, 4);
            p += __shfl_xor_sync(0xffffffffu, p, 8);
            if (tx == 0 && valid) logitOut[gm] = p + b3[0];
        }
    }

    if (DO_MAX) {
        if (anyv) {
#pragma unroll
            for (int j = 0; j < 8; j++) atomicMax(&smax[tx * 8 + j], fkey(colmax[j]));
        }
        __syncthreads();
        if (tid < 128) atomicMax(&g_maxU[n0 + tid], smax[tid]);
    }
}

// ---------------- mask pass: compact hit points ------------------------------
__global__ void mask_kernel(const float* __restrict__ xyz,
                            const float* __restrict__ pc,
                            const float* __restrict__ pn,
                            const float* __restrict__ pmn,
                            const float* __restrict__ pmx, int M)
{
    __shared__ float s_n0[PP], s_n1[PP], s_n2[PP], s_off[PP];
    __shared__ float s_mn0[PP], s_mn1[PP], s_mx0[PP], s_mx1[PP];
    int t = threadIdx.x;
    if (t < PP) {
        float a0 = pn[t * 3], a1 = pn[t * 3 + 1], a2 = pn[t * 3 + 2];
        s_n0[t] = a0; s_n1[t] = a1; s_n2[t] = a2;
        s_off[t] = pc[t * 3] * a0 + pc[t * 3 + 1] * a1 + pc[t * 3 + 2] * a2;
        s_mn0[t] = pmn[t * 3]; s_mn1[t] = pmn[t * 3 + 1];
        s_mx0[t] = pmx[t * 3]; s_mx1[t] = pmx[t * 3 + 1];
    }
    __syncthreads();
    int n = blockIdx.x * blockDim.x + t;
    if (n >= M) return;
    float x = xyz[n * 3], y = xyz[n * 3 + 1], z = xyz[n * 3 + 2];
    unsigned long long mask = 0ull;
#pragma unroll
    for (int p = 0; p < PP; p++) {
        float proj = x * s_n0[p] + y * s_n1[p] + z * s_n2[p];
        bool hit = (fabsf(proj - s_off[p]) < DIST_TH) &&
                   (x >= s_mn0[p]) && (x < s_mx0[p]) &&
                   (y >= s_mn1[p]) && (y < s_mx1[p]);
        if (hit) mask |= (1ull << p);
    }
    if (mask) {
        int pos = atomicAdd(&g_cnt, 1);
        g_idx[pos] = n;
        g_maskArr[pos] = mask;
    }
}

// ---------------- pooling scatter over compacted points ----------------------
__global__ void pool2_kernel(const float* __restrict__ logit)
{
    __shared__ float s_amax[C];
    if (threadIdx.x < C) s_amax[threadIdx.x] = funkey(g_maxU[threadIdx.x]);
    __syncthreads();
    int cnt = g_cnt;
    int stride = gridDim.x * blockDim.x;
    for (int i = blockIdx.x * blockDim.x + threadIdx.x; i < cnt; i += stride) {
        int n = g_idx[i];
        unsigned long long mask = g_maskArr[i];
        bool on = logit[n] > 0.0f;
        float* numB = on ? g_num_on : g_num_off;
        float* denB = on ? g_den_on : g_den_off;
        const float* ar = g_a + (size_t)i * C;
        const float* hr = g_h2 + (size_t)n * C;
        for (int c = 0; c < C; c += 4) {
            float4 a4 = *(const float4*)(ar + c);
            float4 h4 = *(const float4*)(hr + c);
            float e0 = expf(a4.x - s_amax[c + 0]);
            float e1 = expf(a4.y - s_amax[c + 1]);
            float e2 = expf(a4.z - s_amax[c + 2]);
            float e3 = expf(a4.w - s_amax[c + 3]);
            unsigned long long mm = mask;
            while (mm) {
                int p = __ffsll(mm) - 1;
                mm &= mm - 1;
                float* dn = denB + p * C + c;
                float* nm = numB + p * C + c;
                atomicAdd(dn + 0, e0); atomicAdd(dn + 1, e1);
                atomicAdd(dn + 2, e2); atomicAdd(dn + 3, e3);
                atomicAdd(nm + 0, e0 * h4.x); atomicAdd(nm + 1, e1 * h4.y);
                atomicAdd(nm + 2, e2 * h4.z); atomicAdd(nm + 3, e3 * h4.w);
            }
        }
    }
}

// ---------------- finalize: agg -> relu(agg@Wm+bm), concat ori --------------
__global__ void finalize_kernel(const float* __restrict__ Wm,
                                const float* __restrict__ bm,
                                const float* __restrict__ pc,
                                const float* __restrict__ pn,
                                const float* __restrict__ pmn,
                                const float* __restrict__ pmx,
                                float* __restrict__ out, int M)
{
    int p = blockIdx.x;     // 64
    int c = threadIdx.x;    // 128
    __shared__ float aggOn[C], aggOff[C];
    aggOn[c]  = g_num_on [p * C + c] / (g_den_on [p * C + c] + 1e-9f);
    aggOff[c] = g_num_off[p * C + c] / (g_den_off[p * C + c] + 1e-9f);
    __syncthreads();
    float so = 0.f, sf = 0.f;
#pragma unroll 8
    for (int k = 0; k < C; k++) {
        float w = Wm[k * C + c];
        so = fmaf(aggOn[k], w, so);
        sf = fmaf(aggOff[k], w, sf);
    }
    float bb = bm[c];
    float* onRow  = out + M + (size_t)p * (C + 12);
    float* offRow = out + M + (size_t)PP * (C + 12) + (size_t)p * (C + 12);
    onRow[c]  = fmaxf(so + bb, 0.f);
    offRow[c] = fmaxf(sf + bb, 0.f);
    if (c < 12) {
        int axis = c % 3, grp = c / 3;
        const float* src = (grp == 0) ? pc : (grp == 1) ? pn : (grp == 2) ? pmn : pmx;
        float v = src[p * 3 + axis];
        onRow[C + c] = v;
        offRow[C + c] = v;
    }
}

// ---------------- launch ----------------
extern "C" void kernel_launch(void* const* d_in, const int* in_sizes, int n_in,
                              void* d_out, int out_size)
{
    const float* feature = (const float*)d_in[0];
    const float* xyz     = (const float*)d_in[1];
    const float* pc      = (const float*)d_in[2];
    const float* pn      = (const float*)d_in[3];
    const float* pmn     = (const float*)d_in[4];
    const float* pmx     = (const float*)d_in[5];
    const float* W1      = (const float*)d_in[6];
    const float* s1      = (const float*)d_in[7];
    const float* b1      = (const float*)d_in[8];
    const float* W2      = (const float*)d_in[9];
    const float* s2      = (const float*)d_in[10];
    const float* b2      = (const float*)d_in[11];
    const float* W3      = (const float*)d_in[12];
    const float* b3      = (const float*)d_in[13];
    const float* Wa      = (const float*)d_in[14];
    const float* Wm      = (const float*)d_in[15];
    const float* bm      = (const float*)d_in[16];

    int M = in_sizes[1] / 3;            // N = 100000
    float* out = (float*)d_out;

    float *hP, *h2P, *aP;
    cudaGetSymbolAddress((void**)&hP,  g_h);
    cudaGetSymbolAddress((void**)&h2P, g_h2);
    cudaGetSymbolAddress((void**)&aP,  g_a);

    int gx = (M + 127) / 128;           // 782

    init_kernel<<<32, 256>>>();
    // FC1: h = relu((feature@W1)*s1+b1)   [M,128]x[128,256]
    sgemm2_kernel<1, 0, 0, 0><<<dim3(gx, 2), 256>>>(
        feature, W1, s1, b1, nullptr, nullptr, nullptr, hP, M, C, C2);
    // FC2: h2 = relu((h@W2)*s2+b2)  + fused logit -> out[0..M)
    sgemm2_kernel<1, 0, 0, 1><<<dim3(gx, 1), 256>>>(
        hP, W2, s2, b2, W3, b3, out, h2P, M, C2, C);
    // mask + compaction of hit points
    mask_kernel<<<(M + 255) / 256, 256>>>(xyz, pc, pn, pmn, pmx, M);
    // a = h2[idx]@Wa over compacted points + per-channel max (masked-local)
    sgemm2_kernel<0, 1, 1, 0><<<dim3(gx, 1), 256>>>(
        h2P, Wa, nullptr, nullptr, nullptr, nullptr, nullptr, aP, M, C, C);
    // sparse masked softmax pooling scatter
    pool2_kernel<<<256, 256>>>(out);
    // tiny per-plane GEMM + ori concat
    finalize_kernel<<<PP, 128>>>(Wm, bm, pc, pn, pmn, pmx, out, M);
}